// round 9
// baseline (speedup 1.0000x reference)
#include <cuda_runtime.h>
#include <cstdint>
#include <cstddef>

// B=2, N=4096, K=48, Q=20
// inputs : d_in[0]=S (i32), d_in[1]=h (f32), d_in[2]=J (f32), d_in[3]=edge_idx (i32)
// output : d_out = [ U (B) | U_i (B*N*Q) ] fp32
//
// DRAM traffic is the full J tensor regardless of access pattern (128B fill
// granularity vs 80B column stride). Stream J coalescedly via cp.async,
// 2-stage double buffer, with MULTI-TILE persistent blocks: each block owns
// 8 groups and runs one continuous 48-chunk pipeline (drain amortized 4x),
// grid sized to exactly ~1 wave (1024 blocks, ~7/SM) to kill the tail wave.

namespace {
constexpr int Bc = 2;
constexpr int Nc = 4096;
constexpr int Kc = 48;
constexpr int Qc = 20;
constexpr int MAT = Qc * Qc;              // 400 floats
constexpr int G    = 2;                   // groups per tile
constexpr int TSEQ = 4;                   // tiles per block (sequential)
constexpr int GPBLK = G * TSEQ;           // 8 groups per block
constexpr int KCH = 4;                    // k-matrices per chunk
constexpr int NCH = Kc / KCH;             // 12 chunks per tile
constexpr int TOT = NCH * TSEQ;           // 48 chunks per block
constexpr int TPB = G * Qc * KCH;         // 160 threads = (cg, cq, ck)
constexpr int CHUNK_FLOATS = G * KCH * MAT;      // 3200 (12.8 KB)
constexpr int VPT = (CHUNK_FLOATS / 4) / TPB;    // 5 float4 per thread/chunk
constexpr int GROUPS = Bc * Nc;           // 8192
constexpr int NBLK   = GROUPS / GPBLK;    // 1024
constexpr int BLK_PER_B = NBLK / Bc;      // 512
constexpr int TILE_V4 = Kc * MAT / 4;     // 4800 float4 per group
constexpr int CH_V4   = KCH * MAT / 4;    // 400 float4 per (group,chunk)
}

__device__ float g_partial[NBLK];
__device__ int   g_count = 0;             // self-resetting epoch counter

__device__ __forceinline__ unsigned smem_addr(const void* p) {
    return (unsigned)__cvta_generic_to_shared(p);
}
__device__ __forceinline__ void cp16(unsigned dst, const float4* src) {
    asm volatile("cp.async.cg.shared.global [%0], [%1], 16;" :: "r"(dst), "l"(src));
}
__device__ __forceinline__ void cp_commit() {
    asm volatile("cp.async.commit_group;");
}
template <int N>
__device__ __forceinline__ void cp_wait() {
    asm volatile("cp.async.wait_group %0;" :: "n"(N));
}

__global__ __launch_bounds__(TPB)
void potts_stream_kernel(const int* __restrict__ S,
                         const float* __restrict__ h,
                         const float* __restrict__ J,
                         const int* __restrict__ eidx,
                         float* __restrict__ out)
{
    __shared__ float Jsh[2][CHUNK_FLOATS];        // 25.6 KB double buffer
    __shared__ int   s_sh[GPBLK][Kc];             // 1.5 KB neighbor states
    __shared__ float part[GPBLK][Qc][KCH];        // 2.56 KB
    __shared__ float c_sh[GPBLK];
    __shared__ bool  is_last;

    const int tid   = threadIdx.x;
    const int gbase = blockIdx.x * GPBLK;

    // Loader mapping (constant across chunks): float4 f = tid + i*TPB,
    // gg = f/400 (group within tile), rem = f%400.
    const float4* Jv4 = (const float4*)J;
    const float4* l_src[VPT];                     // base for tile 0, chunk 0
    unsigned      l_dst0[VPT];
    #pragma unroll
    for (int i = 0; i < VPT; i++) {
        const int f  = tid + i * TPB;
        const int gg = f / CH_V4;
        const int rm = f - gg * CH_V4;
        l_src[i]  = Jv4 + (size_t)(gbase + gg) * TILE_V4 + rm;
        l_dst0[i] = smem_addr(&Jsh[0][gg * KCH * MAT + rm * 4]);
    }
    // Chunk cc (0..47): tile = cc/NCH, c = cc%NCH. In the fully unrolled
    // loop these fold to immediates in SASS.
    #define ISSUE_CHUNK(cc, buf)                                                  \
        do {                                                                      \
            const int _t = (cc) / NCH, _c = (cc) % NCH;                           \
            _Pragma("unroll")                                                     \
            for (int i = 0; i < VPT; i++)                                         \
                cp16(l_dst0[i] + (buf) * (CHUNK_FLOATS * 4),                      \
                     l_src[i] + (size_t)_t * (G * TILE_V4) + _c * CH_V4);         \
            cp_commit();                                                          \
        } while (0)

    ISSUE_CHUNK(0, 0);
    ISSUE_CHUNK(1, 1);

    // Gather all 8 groups' neighbor states (overlaps with async loads).
    #pragma unroll
    for (int t = tid; t < GPBLK * Kc; t += TPB) {
        const int gg = t / Kc, k = t - gg * Kc;
        const int grp = gbase + gg;
        const int b   = grp >> 12;
        s_sh[gg][k] = S[b * Nc + eidx[(size_t)grp * Kc + k]];
    }

    // Compute mapping: tid = (cg, cq, ck)
    const int cg = tid / (Qc * KCH);
    const int r  = tid - cg * (Qc * KCH);
    const int cq = r / KCH;
    const int ck = r - cq * KCH;
    const int smem_base_idx = cg * KCH * MAT + ck * MAT + cq * Qc;

    // Continuous 48-chunk pipeline across the 4 tiles (no drains between).
    float acc[TSEQ];
    #pragma unroll
    for (int t = 0; t < TSEQ; t++) acc[t] = 0.f;

    #pragma unroll
    for (int cc = 0; cc < TOT; cc++) {
        if (cc < TOT - 1) cp_wait<1>(); else cp_wait<0>();
        __syncthreads();                          // chunk cc visible
        const int t = cc / NCH, c = cc % NCH;
        acc[t] += Jsh[cc & 1][smem_base_idx + s_sh[t * G + cg][c * KCH + ck]];
        __syncthreads();                          // done reading buf cc&1
        if (cc + 2 < TOT) ISSUE_CHUNK(cc + 2, cc & 1);
    }
    #undef ISSUE_CHUNK

    #pragma unroll
    for (int t = 0; t < TSEQ; t++) part[t * G + cg][cq][ck] = acc[t];
    __syncthreads();

    // Epilogue: 160 threads = 8 groups x 20 q.
    {
        const int gg  = tid / Qc, q = tid - gg * Qc;
        const int grp = gbase + gg;
        const float ji = (part[gg][q][0] + part[gg][q][1])
                       + (part[gg][q][2] + part[gg][q][3]);
        const float hv = h[(size_t)grp * Qc + q];
        const float ui = hv + ji;
        out[Bc + (size_t)grp * Qc + q] = ui;
        if (q == S[grp]) c_sh[gg] = 0.5f * (ui + hv);
    }
    __syncthreads();

    if (tid == 0) {
        float s = 0.f;
        #pragma unroll
        for (int g = 0; g < GPBLK; g++) s += c_sh[g];
        g_partial[blockIdx.x] = s;
        __threadfence();
        is_last = (atomicAdd(&g_count, 1) == NBLK - 1);
    }
    __syncthreads();

    if (is_last) {
        float* red = &Jsh[0][0];
        #pragma unroll
        for (int b = 0; b < Bc; b++) {
            float s = 0.f;
            for (int i = tid; i < BLK_PER_B; i += TPB)
                s += g_partial[b * BLK_PER_B + i];
            red[tid] = s;
            __syncthreads();
            if (tid == 0) {
                float t = 0.f;
                #pragma unroll
                for (int i = 0; i < TPB; i++) t += red[i];
                out[b] = t;
            }
            __syncthreads();
        }
        if (tid == 0) g_count = 0;                // reset for next replay
    }
}

extern "C" void kernel_launch(void* const* d_in, const int* in_sizes, int n_in,
                              void* d_out, int out_size)
{
    const int*   S    = (const int*)  d_in[0];
    const float* h    = (const float*)d_in[1];
    const float* J    = (const float*)d_in[2];
    const int*   eidx = (const int*)  d_in[3];
    float*       out  = (float*)      d_out;

    potts_stream_kernel<<<NBLK, TPB>>>(S, h, J, eidx, out);

    (void)in_sizes; (void)n_in; (void)out_size;
}

// round 10
// speedup vs baseline: 1.0003x; 1.0003x over previous
#include <cuda_runtime.h>
#include <cstdint>
#include <cstddef>

// B=2, N=4096, K=48, Q=20
// inputs : d_in[0]=S (i32), d_in[1]=h (f32), d_in[2]=J (f32), d_in[3]=edge_idx (i32)
// output : d_out = [ U (B) | U_i (B*N*Q) ] fp32
//
// DRAM traffic is the full J tensor regardless of access pattern (128B fill
// granularity vs 80B column stride). Stream J coalescedly via cp.async,
// 2-stage double buffer, with MULTI-TILE persistent blocks: each block owns
// 8 groups and runs one continuous 48-chunk pipeline (drain amortized 4x),
// grid sized to exactly ~1 wave (1024 blocks, ~7/SM) to kill the tail wave.

namespace {
constexpr int Bc = 2;
constexpr int Nc = 4096;
constexpr int Kc = 48;
constexpr int Qc = 20;
constexpr int MAT = Qc * Qc;              // 400 floats
constexpr int G    = 2;                   // groups per tile
constexpr int TSEQ = 4;                   // tiles per block (sequential)
constexpr int GPBLK = G * TSEQ;           // 8 groups per block
constexpr int KCH = 4;                    // k-matrices per chunk
constexpr int NCH = Kc / KCH;             // 12 chunks per tile
constexpr int TOT = NCH * TSEQ;           // 48 chunks per block
constexpr int TPB = G * Qc * KCH;         // 160 threads = (cg, cq, ck)
constexpr int CHUNK_FLOATS = G * KCH * MAT;      // 3200 (12.8 KB)
constexpr int VPT = (CHUNK_FLOATS / 4) / TPB;    // 5 float4 per thread/chunk
constexpr int GROUPS = Bc * Nc;           // 8192
constexpr int NBLK   = GROUPS / GPBLK;    // 1024
constexpr int BLK_PER_B = NBLK / Bc;      // 512
constexpr int TILE_V4 = Kc * MAT / 4;     // 4800 float4 per group
constexpr int CH_V4   = KCH * MAT / 4;    // 400 float4 per (group,chunk)
}

__device__ float g_partial[NBLK];
__device__ int   g_count = 0;             // self-resetting epoch counter

__device__ __forceinline__ unsigned smem_addr(const void* p) {
    return (unsigned)__cvta_generic_to_shared(p);
}
__device__ __forceinline__ void cp16(unsigned dst, const float4* src) {
    asm volatile("cp.async.cg.shared.global [%0], [%1], 16;" :: "r"(dst), "l"(src));
}
__device__ __forceinline__ void cp_commit() {
    asm volatile("cp.async.commit_group;");
}
template <int N>
__device__ __forceinline__ void cp_wait() {
    asm volatile("cp.async.wait_group %0;" :: "n"(N));
}

__global__ __launch_bounds__(TPB)
void potts_stream_kernel(const int* __restrict__ S,
                         const float* __restrict__ h,
                         const float* __restrict__ J,
                         const int* __restrict__ eidx,
                         float* __restrict__ out)
{
    __shared__ float Jsh[2][CHUNK_FLOATS];        // 25.6 KB double buffer
    __shared__ int   s_sh[GPBLK][Kc];             // 1.5 KB neighbor states
    __shared__ float part[GPBLK][Qc][KCH];        // 2.56 KB
    __shared__ float c_sh[GPBLK];
    __shared__ bool  is_last;

    const int tid   = threadIdx.x;
    const int gbase = blockIdx.x * GPBLK;

    // Loader mapping (constant across chunks): float4 f = tid + i*TPB,
    // gg = f/400 (group within tile), rem = f%400.
    const float4* Jv4 = (const float4*)J;
    const float4* l_src[VPT];                     // base for tile 0, chunk 0
    unsigned      l_dst0[VPT];
    #pragma unroll
    for (int i = 0; i < VPT; i++) {
        const int f  = tid + i * TPB;
        const int gg = f / CH_V4;
        const int rm = f - gg * CH_V4;
        l_src[i]  = Jv4 + (size_t)(gbase + gg) * TILE_V4 + rm;
        l_dst0[i] = smem_addr(&Jsh[0][gg * KCH * MAT + rm * 4]);
    }
    // Chunk cc (0..47): tile = cc/NCH, c = cc%NCH. In the fully unrolled
    // loop these fold to immediates in SASS.
    #define ISSUE_CHUNK(cc, buf)                                                  \
        do {                                                                      \
            const int _t = (cc) / NCH, _c = (cc) % NCH;                           \
            _Pragma("unroll")                                                     \
            for (int i = 0; i < VPT; i++)                                         \
                cp16(l_dst0[i] + (buf) * (CHUNK_FLOATS * 4),                      \
                     l_src[i] + (size_t)_t * (G * TILE_V4) + _c * CH_V4);         \
            cp_commit();                                                          \
        } while (0)

    ISSUE_CHUNK(0, 0);
    ISSUE_CHUNK(1, 1);

    // Gather all 8 groups' neighbor states (overlaps with async loads).
    #pragma unroll
    for (int t = tid; t < GPBLK * Kc; t += TPB) {
        const int gg = t / Kc, k = t - gg * Kc;
        const int grp = gbase + gg;
        const int b   = grp >> 12;
        s_sh[gg][k] = S[b * Nc + eidx[(size_t)grp * Kc + k]];
    }

    // Compute mapping: tid = (cg, cq, ck)
    const int cg = tid / (Qc * KCH);
    const int r  = tid - cg * (Qc * KCH);
    const int cq = r / KCH;
    const int ck = r - cq * KCH;
    const int smem_base_idx = cg * KCH * MAT + ck * MAT + cq * Qc;

    // Continuous 48-chunk pipeline across the 4 tiles (no drains between).
    float acc[TSEQ];
    #pragma unroll
    for (int t = 0; t < TSEQ; t++) acc[t] = 0.f;

    #pragma unroll
    for (int cc = 0; cc < TOT; cc++) {
        if (cc < TOT - 1) cp_wait<1>(); else cp_wait<0>();
        __syncthreads();                          // chunk cc visible
        const int t = cc / NCH, c = cc % NCH;
        acc[t] += Jsh[cc & 1][smem_base_idx + s_sh[t * G + cg][c * KCH + ck]];
        __syncthreads();                          // done reading buf cc&1
        if (cc + 2 < TOT) ISSUE_CHUNK(cc + 2, cc & 1);
    }
    #undef ISSUE_CHUNK

    #pragma unroll
    for (int t = 0; t < TSEQ; t++) part[t * G + cg][cq][ck] = acc[t];
    __syncthreads();

    // Epilogue: 160 threads = 8 groups x 20 q.
    {
        const int gg  = tid / Qc, q = tid - gg * Qc;
        const int grp = gbase + gg;
        const float ji = (part[gg][q][0] + part[gg][q][1])
                       + (part[gg][q][2] + part[gg][q][3]);
        const float hv = h[(size_t)grp * Qc + q];
        const float ui = hv + ji;
        out[Bc + (size_t)grp * Qc + q] = ui;
        if (q == S[grp]) c_sh[gg] = 0.5f * (ui + hv);
    }
    __syncthreads();

    if (tid == 0) {
        float s = 0.f;
        #pragma unroll
        for (int g = 0; g < GPBLK; g++) s += c_sh[g];
        g_partial[blockIdx.x] = s;
        __threadfence();
        is_last = (atomicAdd(&g_count, 1) == NBLK - 1);
    }
    __syncthreads();

    if (is_last) {
        float* red = &Jsh[0][0];
        #pragma unroll
        for (int b = 0; b < Bc; b++) {
            float s = 0.f;
            for (int i = tid; i < BLK_PER_B; i += TPB)
                s += g_partial[b * BLK_PER_B + i];
            red[tid] = s;
            __syncthreads();
            if (tid == 0) {
                float t = 0.f;
                #pragma unroll
                for (int i = 0; i < TPB; i++) t += red[i];
                out[b] = t;
            }
            __syncthreads();
        }
        if (tid == 0) g_count = 0;                // reset for next replay
    }
}

extern "C" void kernel_launch(void* const* d_in, const int* in_sizes, int n_in,
                              void* d_out, int out_size)
{
    const int*   S    = (const int*)  d_in[0];
    const float* h    = (const float*)d_in[1];
    const float* J    = (const float*)d_in[2];
    const int*   eidx = (const int*)  d_in[3];
    float*       out  = (float*)      d_out;

    potts_stream_kernel<<<NBLK, TPB>>>(S, h, J, eidx, out);

    (void)in_sizes; (void)n_in; (void)out_size;
}

// round 11
// speedup vs baseline: 1.0046x; 1.0043x over previous
#include <cuda_runtime.h>
#include <cstdint>
#include <cstddef>

// B=2, N=4096, K=48, Q=20
// inputs : d_in[0]=S (i32), d_in[1]=h (f32), d_in[2]=J (f32), d_in[3]=edge_idx (i32)
// output : d_out = [ U (B) | U_i (B*N*Q) ] fp32
//
// DRAM traffic is the full J tensor regardless of access pattern (128B fill
// granularity vs 80B column stride). Stream J coalescedly via cp.async,
// 2-stage double buffer, with MULTI-TILE persistent blocks: each block owns
// 8 groups and runs one continuous 48-chunk pipeline (drain amortized 4x),
// grid sized to exactly ~1 wave (1024 blocks, ~7/SM) to kill the tail wave.

namespace {
constexpr int Bc = 2;
constexpr int Nc = 4096;
constexpr int Kc = 48;
constexpr int Qc = 20;
constexpr int MAT = Qc * Qc;              // 400 floats
constexpr int G    = 2;                   // groups per tile
constexpr int TSEQ = 4;                   // tiles per block (sequential)
constexpr int GPBLK = G * TSEQ;           // 8 groups per block
constexpr int KCH = 4;                    // k-matrices per chunk
constexpr int NCH = Kc / KCH;             // 12 chunks per tile
constexpr int TOT = NCH * TSEQ;           // 48 chunks per block
constexpr int TPB = G * Qc * KCH;         // 160 threads = (cg, cq, ck)
constexpr int CHUNK_FLOATS = G * KCH * MAT;      // 3200 (12.8 KB)
constexpr int VPT = (CHUNK_FLOATS / 4) / TPB;    // 5 float4 per thread/chunk
constexpr int GROUPS = Bc * Nc;           // 8192
constexpr int NBLK   = GROUPS / GPBLK;    // 1024
constexpr int BLK_PER_B = NBLK / Bc;      // 512
constexpr int TILE_V4 = Kc * MAT / 4;     // 4800 float4 per group
constexpr int CH_V4   = KCH * MAT / 4;    // 400 float4 per (group,chunk)
}

__device__ float g_partial[NBLK];
__device__ int   g_count = 0;             // self-resetting epoch counter

__device__ __forceinline__ unsigned smem_addr(const void* p) {
    return (unsigned)__cvta_generic_to_shared(p);
}
__device__ __forceinline__ void cp16(unsigned dst, const float4* src) {
    asm volatile("cp.async.cg.shared.global [%0], [%1], 16;" :: "r"(dst), "l"(src));
}
__device__ __forceinline__ void cp_commit() {
    asm volatile("cp.async.commit_group;");
}
template <int N>
__device__ __forceinline__ void cp_wait() {
    asm volatile("cp.async.wait_group %0;" :: "n"(N));
}

__global__ __launch_bounds__(TPB)
void potts_stream_kernel(const int* __restrict__ S,
                         const float* __restrict__ h,
                         const float* __restrict__ J,
                         const int* __restrict__ eidx,
                         float* __restrict__ out)
{
    __shared__ float Jsh[2][CHUNK_FLOATS];        // 25.6 KB double buffer
    __shared__ int   s_sh[GPBLK][Kc];             // 1.5 KB neighbor states
    __shared__ float part[GPBLK][Qc][KCH];        // 2.56 KB
    __shared__ float c_sh[GPBLK];
    __shared__ bool  is_last;

    const int tid   = threadIdx.x;
    const int gbase = blockIdx.x * GPBLK;

    // Loader mapping (constant across chunks): float4 f = tid + i*TPB,
    // gg = f/400 (group within tile), rem = f%400.
    const float4* Jv4 = (const float4*)J;
    const float4* l_src[VPT];                     // base for tile 0, chunk 0
    unsigned      l_dst0[VPT];
    #pragma unroll
    for (int i = 0; i < VPT; i++) {
        const int f  = tid + i * TPB;
        const int gg = f / CH_V4;
        const int rm = f - gg * CH_V4;
        l_src[i]  = Jv4 + (size_t)(gbase + gg) * TILE_V4 + rm;
        l_dst0[i] = smem_addr(&Jsh[0][gg * KCH * MAT + rm * 4]);
    }
    // Chunk cc (0..47): tile = cc/NCH, c = cc%NCH. In the fully unrolled
    // loop these fold to immediates in SASS.
    #define ISSUE_CHUNK(cc, buf)                                                  \
        do {                                                                      \
            const int _t = (cc) / NCH, _c = (cc) % NCH;                           \
            _Pragma("unroll")                                                     \
            for (int i = 0; i < VPT; i++)                                         \
                cp16(l_dst0[i] + (buf) * (CHUNK_FLOATS * 4),                      \
                     l_src[i] + (size_t)_t * (G * TILE_V4) + _c * CH_V4);         \
            cp_commit();                                                          \
        } while (0)

    ISSUE_CHUNK(0, 0);
    ISSUE_CHUNK(1, 1);

    // Gather all 8 groups' neighbor states (overlaps with async loads).
    #pragma unroll
    for (int t = tid; t < GPBLK * Kc; t += TPB) {
        const int gg = t / Kc, k = t - gg * Kc;
        const int grp = gbase + gg;
        const int b   = grp >> 12;
        s_sh[gg][k] = S[b * Nc + eidx[(size_t)grp * Kc + k]];
    }

    // Compute mapping: tid = (cg, cq, ck)
    const int cg = tid / (Qc * KCH);
    const int r  = tid - cg * (Qc * KCH);
    const int cq = r / KCH;
    const int ck = r - cq * KCH;
    const int smem_base_idx = cg * KCH * MAT + ck * MAT + cq * Qc;

    // Continuous 48-chunk pipeline across the 4 tiles (no drains between).
    float acc[TSEQ];
    #pragma unroll
    for (int t = 0; t < TSEQ; t++) acc[t] = 0.f;

    #pragma unroll
    for (int cc = 0; cc < TOT; cc++) {
        if (cc < TOT - 1) cp_wait<1>(); else cp_wait<0>();
        __syncthreads();                          // chunk cc visible
        const int t = cc / NCH, c = cc % NCH;
        acc[t] += Jsh[cc & 1][smem_base_idx + s_sh[t * G + cg][c * KCH + ck]];
        __syncthreads();                          // done reading buf cc&1
        if (cc + 2 < TOT) ISSUE_CHUNK(cc + 2, cc & 1);
    }
    #undef ISSUE_CHUNK

    #pragma unroll
    for (int t = 0; t < TSEQ; t++) part[t * G + cg][cq][ck] = acc[t];
    __syncthreads();

    // Epilogue: 160 threads = 8 groups x 20 q.
    {
        const int gg  = tid / Qc, q = tid - gg * Qc;
        const int grp = gbase + gg;
        const float ji = (part[gg][q][0] + part[gg][q][1])
                       + (part[gg][q][2] + part[gg][q][3]);
        const float hv = h[(size_t)grp * Qc + q];
        const float ui = hv + ji;
        out[Bc + (size_t)grp * Qc + q] = ui;
        if (q == S[grp]) c_sh[gg] = 0.5f * (ui + hv);
    }
    __syncthreads();

    if (tid == 0) {
        float s = 0.f;
        #pragma unroll
        for (int g = 0; g < GPBLK; g++) s += c_sh[g];
        g_partial[blockIdx.x] = s;
        __threadfence();
        is_last = (atomicAdd(&g_count, 1) == NBLK - 1);
    }
    __syncthreads();

    if (is_last) {
        float* red = &Jsh[0][0];
        #pragma unroll
        for (int b = 0; b < Bc; b++) {
            float s = 0.f;
            for (int i = tid; i < BLK_PER_B; i += TPB)
                s += g_partial[b * BLK_PER_B + i];
            red[tid] = s;
            __syncthreads();
            if (tid == 0) {
                float t = 0.f;
                #pragma unroll
                for (int i = 0; i < TPB; i++) t += red[i];
                out[b] = t;
            }
            __syncthreads();
        }
        if (tid == 0) g_count = 0;                // reset for next replay
    }
}

extern "C" void kernel_launch(void* const* d_in, const int* in_sizes, int n_in,
                              void* d_out, int out_size)
{
    const int*   S    = (const int*)  d_in[0];
    const float* h    = (const float*)d_in[1];
    const float* J    = (const float*)d_in[2];
    const int*   eidx = (const int*)  d_in[3];
    float*       out  = (float*)      d_out;

    potts_stream_kernel<<<NBLK, TPB>>>(S, h, J, eidx, out);

    (void)in_sizes; (void)n_in; (void)out_size;
}